// round 11
// baseline (speedup 1.0000x reference)
#include <cuda_runtime.h>
#include <cstddef>

// Problem constants
constexpr int Bv = 64, Tv = 168, Nv = 64, Fv = 17, Hv = 128;
constexpr int BT = Bv * Tv;            // 10752
constexpr int G4 = 4 * Hv;             // 512 gate units
constexpr int NL = 4;

// Scratch (device globals — no allocation allowed)
__device__ float g_seqA[BT * Hv];
__device__ float g_seqB[BT * Hv];
__device__ float g_proj[BT * G4];
__device__ float g_hfinal[NL * Bv * Hv];
__device__ float g_WhhT[NL * G4 * Hv];
__device__ float g_w2a[Hv];
__device__ float g_w2b[Hv];
__device__ unsigned long long g_msk[Nv];

// ---------------------------------------------------------------------------
// packed f32x2 FMA (Blackwell; only reachable via PTX)
union F2U { float2 f; unsigned long long u; };
__device__ __forceinline__ unsigned long long pack2(float a, float b) {
    F2U v; v.f = make_float2(a, b); return v.u;
}
__device__ __forceinline__ void fma2(unsigned long long& acc,
                                     unsigned long long a,
                                     unsigned long long b) {
    asm("fma.rn.f32x2 %0, %1, %2, %3;" : "=l"(acc) : "l"(a), "l"(b), "l"(acc));
}

// ---------------------------------------------------------------------------
// Precompute adjacency bitmask (adj>0 || i==j)
__global__ void mask_kernel(const int* __restrict__ adj,
                            unsigned long long* __restrict__ msk) {
    int i = threadIdx.x;
    if (i >= Nv) return;
    unsigned long long m = 0ull;
    for (int j = 0; j < Nv; ++j)
        if (adj[i * Nv + j] > 0 || j == i) m |= (1ull << j);
    msk[i] = m;
}

// ---------------------------------------------------------------------------
// w2a[k] = sum_o W2[k][o]*a2[H+o] ; w2b[k] = sum_o W2[k][o]*a2[o]
__global__ void w2vec_kernel(const float* __restrict__ W2,
                             const float* __restrict__ a2,
                             float* __restrict__ w2a,
                             float* __restrict__ w2b) {
    int tid = threadIdx.x;        // 256 threads
    int k = tid & 127;
    const float* av = (tid < 128) ? (a2 + Hv) : a2;
    float acc = 0.f;
    for (int o = 0; o < Hv; ++o)
        acc += W2[(size_t)k * Hv + o] * av[o];
    if (tid < 128) w2a[k] = acc; else w2b[k] = acc;
}

// ---------------------------------------------------------------------------
// Transpose Whh[l][u][k] -> WT[l][k/4][u][4] (float4 per (kb,u))
__global__ void transpose_whh_kernel(const float* __restrict__ Whh,
                                     float* __restrict__ WT) {
    int idx = blockIdx.x * 256 + threadIdx.x;
    if (idx >= NL * G4 * Hv) return;
    int l  = idx >> 16;
    int r  = idx & 65535;
    int kb = r >> 11;
    int r2 = r & 2047;
    int u  = r2 >> 2;
    int i  = r2 & 3;
    WT[idx] = Whh[l * 65536 + u * Hv + kb * 4 + i];
}

// ---------------------------------------------------------------------------
// Fused GAT1 + GAT2 per (b,t), algebraically reduced: GAT2's GEMM and full
// aggregation are folded into vector functionals of GAT1's h.
constexpr int SH = 132;
constexpr int GAT_FLOATS = 64 * SH          // s_h
                         + 64 * 65          // s_attn
                         + Nv * Fv          // s_x
                         + 7 * 64           // src,dst,hw,hw2,d2,arow,c
                         + 128              // s_v
                         + 4;               // scal
constexpr int GAT_SMEM = GAT_FLOATS * 4 + Nv * 8;

__global__ __launch_bounds__(256)
void gat_kernel(const float* __restrict__ x,
                const float* __restrict__ W1, const float* __restrict__ a1,
                const float* __restrict__ W2,
                const float* __restrict__ w2a, const float* __restrict__ w2b,
                const int* __restrict__ site_ptr,
                const unsigned long long* __restrict__ gmsk,
                float* __restrict__ seq_out) {
    extern __shared__ float sm[];
    float* s_h    = sm;                       // 64 x SH
    float* s_attn = s_h   + 64 * SH;          // 64 x 65
    float* s_x    = s_attn + 64 * 65;         // 64 x 17
    float* s_src  = s_x   + Nv * Fv;          // 64
    float* s_dst  = s_src + 64;               // 64
    float* s_hw   = s_dst + 64;               // 64
    float* s_hw2  = s_hw  + 64;               // 64
    float* s_d2   = s_hw2 + 64;               // 64
    float* s_arow = s_d2  + 64;               // 64
    float* s_c    = s_arow + 64;              // 64
    float* s_v    = s_c   + 64;               // 128
    float* s_scal = s_v   + 128;              // 4
    unsigned long long* s_msk =
        (unsigned long long*)(s_scal + 4);    // 64

    const int tid  = threadIdx.x;
    const int w    = tid >> 5;
    const int lane = tid & 31;
    const int bt   = blockIdx.x;

    // load x tile + mask
    const float* xp = x + (size_t)bt * Nv * Fv;
    for (int i = tid; i < Nv * Fv; i += 256) s_x[i] = xp[i];
    if (tid < Nv) s_msk[tid] = gmsk[tid];
    __syncthreads();

    // GEMM1: h[n][o] = sum_f x[n][f] * W1[f][o]
    for (int idx = tid; idx < Nv * Hv; idx += 256) {
        int n = idx >> 7, o = idx & 127;
        float acc = 0.f;
#pragma unroll
        for (int f = 0; f < Fv; ++f)
            acc += s_x[n * Fv + f] * __ldg(&W1[f * Hv + o]);
        s_h[n * SH + o] = acc;
    }
    __syncthreads();

    // 4 groups of 64 threads: src1, dst1, hw = h.w2a, hw2 = h.w2b
    {
        int grp = tid >> 6;
        int n = tid & 63;
        const float* vec = (grp == 0) ? a1
                         : (grp == 1) ? (a1 + Hv)
                         : (grp == 2) ? w2a : w2b;
        const float4* row = (const float4*)(s_h + n * SH);
        const float4* v4  = (const float4*)vec;
        float acc = 0.f;
#pragma unroll 8
        for (int i = 0; i < 32; ++i) {
            float4 hv = row[i];
            float4 av = __ldg(&v4[i]);
            acc += hv.x * av.x + hv.y * av.y + hv.z * av.z + hv.w * av.w;
        }
        float* dsts[4] = { s_src, s_dst, s_hw, s_hw2 };
        dsts[grp][n] = acc;
    }
    __syncthreads();

    // attn1 rows (softmax over j), 8 rows per warp
    for (int i = w; i < Nv; i += 8) {
        unsigned long long m = s_msk[i];
        float si = s_src[i];
        int j0 = lane, j1 = lane + 32;
        float v0 = si + s_dst[j0]; v0 = v0 > 0.f ? v0 : 0.2f * v0;
        float v1 = si + s_dst[j1]; v1 = v1 > 0.f ? v1 : 0.2f * v1;
        float e0 = ((m >> j0) & 1ull) ? v0 : -1e9f;
        float e1 = ((m >> j1) & 1ull) ? v1 : -1e9f;
        float mx = fmaxf(e0, e1);
#pragma unroll
        for (int off = 16; off; off >>= 1)
            mx = fmaxf(mx, __shfl_xor_sync(0xffffffffu, mx, off));
        float p0 = __expf(e0 - mx), p1 = __expf(e1 - mx);
        float s = p0 + p1;
#pragma unroll
        for (int off = 16; off; off >>= 1)
            s += __shfl_xor_sync(0xffffffffu, s, off);
        float inv = 1.f / s;
        s_attn[i * 65 + j0] = p0 * inv;
        s_attn[i * 65 + j1] = p1 * inv;
    }
    __syncthreads();

    // dst2[i] = attn1[i,:] . hw ;  src2 = attn1[site,:] . hw2
    int site = __ldg(site_ptr);
    if (tid < 64) {
        float acc = 0.f;
#pragma unroll 8
        for (int j = 0; j < Nv; ++j)
            acc += s_attn[tid * 65 + j] * s_hw[j];
        s_d2[tid] = acc;
    } else if (tid == 64) {
        float acc = 0.f;
#pragma unroll 8
        for (int j = 0; j < Nv; ++j)
            acc += s_attn[site * 65 + j] * s_hw2[j];
        s_scal[0] = acc;
    }
    __syncthreads();

    // attn2 row for row=site
    if (w == 0) {
        unsigned long long m = s_msk[site];
        float ss = s_scal[0];
        int j0 = lane, j1 = lane + 32;
        float v0 = ss + s_d2[j0]; v0 = v0 > 0.f ? v0 : 0.2f * v0;
        float v1 = ss + s_d2[j1]; v1 = v1 > 0.f ? v1 : 0.2f * v1;
        float e0 = ((m >> j0) & 1ull) ? v0 : -1e9f;
        float e1 = ((m >> j1) & 1ull) ? v1 : -1e9f;
        float mx = fmaxf(e0, e1);
#pragma unroll
        for (int off = 16; off; off >>= 1)
            mx = fmaxf(mx, __shfl_xor_sync(0xffffffffu, mx, off));
        float p0 = __expf(e0 - mx), p1 = __expf(e1 - mx);
        float s = p0 + p1;
#pragma unroll
        for (int off = 16; off; off >>= 1)
            s += __shfl_xor_sync(0xffffffffu, s, off);
        float inv = 1.f / s;
        s_arow[j0] = p0 * inv;
        s_arow[j1] = p1 * inv;
    }
    __syncthreads();

    // c[j] = sum_i arow[i] * attn1[i,j]
    if (tid < 64) {
        float acc = 0.f;
#pragma unroll 8
        for (int i = 0; i < Nv; ++i)
            acc += s_arow[i] * s_attn[i * 65 + tid];
        s_c[tid] = acc;
    }
    __syncthreads();

    // v[o] = sum_j c[j] * h[j][o]
    if (tid < Hv) {
        float acc = 0.f;
#pragma unroll 8
        for (int j = 0; j < Nv; ++j)
            acc += s_c[j] * s_h[j * SH + tid];
        s_v[tid] = acc;
    }
    __syncthreads();

    // out[o] = sum_k v[k] * W2[k][o]  (split k over 2 half-groups)
    {
        int o = tid & 127, hf = tid >> 7;
        float acc = 0.f;
        int k0 = hf * 64;
#pragma unroll 8
        for (int k = 0; k < 64; ++k)
            acc += s_v[k0 + k] * __ldg(&W2[(size_t)(k0 + k) * Hv + o]);
        if (hf == 1) s_hw[o] = acc;   // s_hw free now; reuse as partial buf
        __syncthreads();
        if (hf == 0)
            seq_out[(size_t)bt * Hv + o] = acc + s_hw[o];
    }
}

// ---------------------------------------------------------------------------
// Input projection per layer: proj[row][u] = sum_k seq[row][k]*Wih[u][k] + b[u]
constexpr int PROJ_SMEM = (128 * 129 + 64 * 129) * 4;

__global__ __launch_bounds__(256, 2)
void proj_kernel(const float* __restrict__ seqin,
                 const float* __restrict__ Wih_l,
                 const float* __restrict__ bih_l,
                 const float* __restrict__ bhh_l,
                 float* __restrict__ proj) {
    extern __shared__ float sp[];
    float* s_in = sp;               // 128 x 129
    float* s_w  = sp + 128 * 129;   // 64 x 129
    int tid  = threadIdx.x;
    int row0 = blockIdx.x * 128;
    int u0b  = blockIdx.y * 64;

    for (int i = tid; i < 128 * 128; i += 256) {
        int r = i >> 7, k = i & 127;
        s_in[r * 129 + k] = seqin[(size_t)(row0 + r) * Hv + k];
    }
    for (int i = tid; i < 64 * 128; i += 256) {
        int u = i >> 7, k = i & 127;
        s_w[u * 129 + k] = Wih_l[(size_t)(u0b + u) * Hv + k];
    }
    __syncthreads();

    int r0 = (tid >> 4) * 8;
    int u0 = (tid & 15) * 4;
    float4 acc[8];
#pragma unroll
    for (int r = 0; r < 8; ++r) acc[r] = make_float4(0.f, 0.f, 0.f, 0.f);
#pragma unroll 2
    for (int k = 0; k < Hv; ++k) {
        float w0 = s_w[(u0 + 0) * 129 + k];
        float w1 = s_w[(u0 + 1) * 129 + k];
        float w2 = s_w[(u0 + 2) * 129 + k];
        float w3 = s_w[(u0 + 3) * 129 + k];
#pragma unroll
        for (int r = 0; r < 8; ++r) {
            float hv = s_in[(r0 + r) * 129 + k];
            acc[r].x += hv * w0; acc[r].y += hv * w1;
            acc[r].z += hv * w2; acc[r].w += hv * w3;
        }
    }
    float b0 = bih_l[u0b + u0 + 0] + bhh_l[u0b + u0 + 0];
    float b1 = bih_l[u0b + u0 + 1] + bhh_l[u0b + u0 + 1];
    float b2 = bih_l[u0b + u0 + 2] + bhh_l[u0b + u0 + 2];
    float b3 = bih_l[u0b + u0 + 3] + bhh_l[u0b + u0 + 3];
#pragma unroll
    for (int r = 0; r < 8; ++r) {
        float4 v = acc[r];
        v.x += b0; v.y += b1; v.z += b2; v.w += b3;
        *(float4*)(&proj[(size_t)(row0 + r0 + r) * G4 + u0b + u0]) = v;
    }
}

// ---------------------------------------------------------------------------
__device__ __forceinline__ float sigm_fast(float x) {
    return 1.f / (1.f + __expf(-x));
}
__device__ __forceinline__ float tanh_fast(float x) {
    float t = __expf(2.f * fminf(fmaxf(x, -15.f), 15.f));
    return __fdividef(t - 1.f, t + 1.f);
}

// LSTM recurrence: one block per 2 batches, 512 threads = one gate unit each
// (shared weight loads serve both batches; packed f32x2 FMA).
__global__ __launch_bounds__(512)
void lstm_kernel(const float* __restrict__ proj,      // [B*T*512]
                 const float4* __restrict__ WT4,      // [(k/4)][512] float4
                 float* __restrict__ seq_out,         // [B*T*128]
                 float* __restrict__ hfin) {          // [B*128]
    __shared__ __align__(16) float hsm[2][Hv];
    __shared__ float gsm[2][G4];
    const int u  = threadIdx.x;
    const int b0 = blockIdx.x * 2;
    float c = 0.f;                 // cell state for (u>>7, u&127) when u<256
    if (u < Hv) { hsm[0][u] = 0.f; hsm[1][u] = 0.f; }
    __syncthreads();
    const float4* h04 = (const float4*)hsm[0];
    const float4* h14 = (const float4*)hsm[1];
    const float* p0 = proj + (size_t)b0 * Tv * G4;
    const float* p1 = p0 + (size_t)Tv * G4;

    const int bb = u >> 7;         // for elementwise phase (u<256)
    const int un = u & 127;

    for (int t = 0; t < Tv; ++t) {
        unsigned long long a0a = pack2(p0[(size_t)t * G4 + u], 0.f);
        unsigned long long a0b = pack2(0.f, 0.f);
        unsigned long long a1a = pack2(p1[(size_t)t * G4 + u], 0.f);
        unsigned long long a1b = pack2(0.f, 0.f);
#pragma unroll 8
        for (int kb = 0; kb < 32; ++kb) {
            float4 wv = __ldg(&WT4[kb * G4 + u]);
            float4 h0 = h04[kb];
            float4 h1 = h14[kb];
            unsigned long long wxy = pack2(wv.x, wv.y);
            unsigned long long wzw = pack2(wv.z, wv.w);
            fma2(a0a, wxy, pack2(h0.x, h0.y));
            fma2(a0b, wzw, pack2(h0.z, h0.w));
            fma2(a1a, wxy, pack2(h1.x, h1.y));
            fma2(a1b, wzw, pack2(h1.z, h1.w));
        }
        F2U r0a{.u = a0a}, r0b{.u = a0b}, r1a{.u = a1a}, r1b{.u = a1b};
        gsm[0][u] = r0a.f.x + r0a.f.y + r0b.f.x + r0b.f.y;
        gsm[1][u] = r1a.f.x + r1a.f.y + r1b.f.x + r1b.f.y;
        __syncthreads();
        if (u < 256) {
            float gi = gsm[bb][un];
            float gf = gsm[bb][Hv + un];
            float gg = gsm[bb][2 * Hv + un];
            float go = gsm[bb][3 * Hv + un];
            c = sigm_fast(gf) * c + sigm_fast(gi) * tanh_fast(gg);
            float h = sigm_fast(go) * tanh_fast(c);
            hsm[bb][un] = h;
            seq_out[((size_t)(b0 + bb) * Tv + t) * Hv + un] = h;
            if (t == Tv - 1) hfin[(size_t)(b0 + bb) * Hv + un] = h;
        }
        __syncthreads();
    }
}

// ---------------------------------------------------------------------------
__global__ void final_kernel(const float* __restrict__ hf,
                             const float* __restrict__ Wlin,
                             const float* __restrict__ blin,
                             float* __restrict__ out) {
    int b = threadIdx.x;
    if (b >= Bv) return;
    float acc = blin[0];
    for (int l = 0; l < NL; ++l)
        for (int k = 0; k < Hv; ++k)
            acc += hf[(size_t)l * Bv * Hv + b * Hv + k] * Wlin[l * Hv + k];
    out[b] = acc;
}

// ---------------------------------------------------------------------------
extern "C" void kernel_launch(void* const* d_in, const int* in_sizes, int n_in,
                              void* d_out, int out_size) {
    const float* x    = (const float*)d_in[0];
    const int*   adj  = (const int*)d_in[1];
    const float* W1   = (const float*)d_in[2];
    const float* a1   = (const float*)d_in[3];
    const float* W2   = (const float*)d_in[4];
    const float* a2   = (const float*)d_in[5];
    const float* Wih  = (const float*)d_in[6];
    const float* Whh  = (const float*)d_in[7];
    const float* bih  = (const float*)d_in[8];
    const float* bhh  = (const float*)d_in[9];
    const float* Wlin = (const float*)d_in[10];
    const float* blin = (const float*)d_in[11];
    const int*   site = (const int*)d_in[12];
    float* out = (float*)d_out;

    float *pA, *pB, *pP, *pHF, *pWT, *pW2a, *pW2b;
    unsigned long long* pM;
    cudaGetSymbolAddress((void**)&pA,   g_seqA);
    cudaGetSymbolAddress((void**)&pB,   g_seqB);
    cudaGetSymbolAddress((void**)&pP,   g_proj);
    cudaGetSymbolAddress((void**)&pHF,  g_hfinal);
    cudaGetSymbolAddress((void**)&pWT,  g_WhhT);
    cudaGetSymbolAddress((void**)&pW2a, g_w2a);
    cudaGetSymbolAddress((void**)&pW2b, g_w2b);
    cudaGetSymbolAddress((void**)&pM,   g_msk);

    cudaFuncSetAttribute(gat_kernel,
                         cudaFuncAttributeMaxDynamicSharedMemorySize, GAT_SMEM);
    cudaFuncSetAttribute(proj_kernel,
                         cudaFuncAttributeMaxDynamicSharedMemorySize, PROJ_SMEM);

    mask_kernel<<<1, 64>>>(adj, pM);
    w2vec_kernel<<<1, 256>>>(W2, a2, pW2a, pW2b);
    transpose_whh_kernel<<<(NL * G4 * Hv + 255) / 256, 256>>>(Whh, pWT);
    gat_kernel<<<BT, 256, GAT_SMEM>>>(x, W1, a1, W2, pW2a, pW2b, site, pM, pA);

    for (int l = 0; l < NL; ++l) {
        const float* sin  = (l & 1) ? pB : pA;
        float*       sout = (l & 1) ? pA : pB;
        proj_kernel<<<dim3(BT / 128, G4 / 64), 256, PROJ_SMEM>>>(
            sin, Wih + (size_t)l * G4 * Hv, bih + l * G4, bhh + l * G4, pP);
        lstm_kernel<<<Bv / 2, G4>>>(
            pP, (const float4*)(pWT + (size_t)l * G4 * Hv),
            sout, pHF + (size_t)l * Bv * Hv);
    }
    final_kernel<<<1, 64>>>(pHF, Wlin, blin, out);
}

// round 14
// speedup vs baseline: 1.7192x; 1.7192x over previous
#include <cuda_runtime.h>
#include <cstddef>

// Problem constants
constexpr int Bv = 64, Tv = 168, Nv = 64, Fv = 17, Hv = 128;
constexpr int BT = Bv * Tv;            // 10752
constexpr int G4 = 4 * Hv;             // 512 gate units
constexpr int NL = 4;
constexpr int KW = 256;                // fused gate dot width (x:128 | h:128)
constexpr int WC_PER_L = G4 * KW;      // 131072 floats per layer

// Scratch (device globals — no allocation allowed)
__device__ float g_seqA[BT * Hv];                 // GAT output (layer-0 x)
__device__ float g_hseq[NL * BT * Hv];            // per-layer h sequences
__device__ float g_hfinal[NL * Bv * Hv];
__device__ float g_WC[NL * WC_PER_L];             // fused [l][kb][u][4]
__device__ float g_bsum[NL * G4];
__device__ float g_w2a[Hv];
__device__ float g_w2b[Hv];
__device__ unsigned long long g_msk[Nv];
__device__ int   g_flags[NL * 32];                // progress per (layer, pair)

// ---------------------------------------------------------------------------
// packed f32x2 FMA (Blackwell; only reachable via PTX)
union F2U { float2 f; unsigned long long u; };
__device__ __forceinline__ void fma2(unsigned long long& acc,
                                     unsigned long long a,
                                     unsigned long long b) {
    asm("fma.rn.f32x2 %0, %1, %2, %3;" : "=l"(acc) : "l"(a), "l"(b), "l"(acc));
}

// ---------------------------------------------------------------------------
__global__ void mask_kernel(const int* __restrict__ adj,
                            unsigned long long* __restrict__ msk) {
    int i = threadIdx.x;
    if (i >= Nv) return;
    unsigned long long m = 0ull;
    for (int j = 0; j < Nv; ++j)
        if (adj[i * Nv + j] > 0 || j == i) m |= (1ull << j);
    msk[i] = m;
}

// ---------------------------------------------------------------------------
__global__ void w2vec_kernel(const float* __restrict__ W2,
                             const float* __restrict__ a2,
                             float* __restrict__ w2a,
                             float* __restrict__ w2b) {
    int tid = threadIdx.x;        // 256 threads
    int k = tid & 127;
    const float* av = (tid < 128) ? (a2 + Hv) : a2;
    float acc = 0.f;
    for (int o = 0; o < Hv; ++o)
        acc += W2[(size_t)k * Hv + o] * av[o];
    if (tid < 128) w2a[k] = acc; else w2b[k] = acc;
}

// ---------------------------------------------------------------------------
// Build fused transposed weights: WC[l][kb][u][i] with k = kb*4+i,
// k<128 -> Wih[l][u][k], k>=128 -> Whh[l][u][k-128]. Also bsum.
__global__ void build_wc_kernel(const float* __restrict__ Wih,
                                const float* __restrict__ Whh,
                                float* __restrict__ WC) {
    int idx = blockIdx.x * 256 + threadIdx.x;
    if (idx >= NL * WC_PER_L) return;
    int l  = idx >> 17;            // / 131072
    int r  = idx & 131071;
    int kb = r >> 11;              // / 2048
    int r2 = r & 2047;
    int u  = r2 >> 2;
    int i  = r2 & 3;
    int k  = kb * 4 + i;
    float v;
    if (k < Hv) v = Wih[((size_t)l * G4 + u) * Hv + k];
    else        v = Whh[((size_t)l * G4 + u) * Hv + (k - Hv)];
    WC[idx] = v;
}

__global__ void bsum_kernel(const float* __restrict__ bih,
                            const float* __restrict__ bhh,
                            float* __restrict__ bsum) {
    int idx = blockIdx.x * 256 + threadIdx.x;
    if (idx < NL * G4) bsum[idx] = bih[idx] + bhh[idx];
}

__global__ void flaginit_kernel(int* __restrict__ flags) {
    if (threadIdx.x < NL * 32) flags[threadIdx.x] = 0;
}

// ---------------------------------------------------------------------------
// Fused GAT1 + GAT2 per (b,t) — unchanged from R11 (417us, not the bottleneck)
constexpr int SH = 132;
constexpr int GAT_FLOATS = 64 * SH + 64 * 65 + Nv * Fv + 7 * 64 + 128 + 4;
constexpr int GAT_SMEM = GAT_FLOATS * 4 + Nv * 8;

__global__ __launch_bounds__(256)
void gat_kernel(const float* __restrict__ x,
                const float* __restrict__ W1, const float* __restrict__ a1,
                const float* __restrict__ W2,
                const float* __restrict__ w2a, const float* __restrict__ w2b,
                const int* __restrict__ site_ptr,
                const unsigned long long* __restrict__ gmsk,
                float* __restrict__ seq_out) {
    extern __shared__ float sm[];
    float* s_h    = sm;
    float* s_attn = s_h   + 64 * SH;
    float* s_x    = s_attn + 64 * 65;
    float* s_src  = s_x   + Nv * Fv;
    float* s_dst  = s_src + 64;
    float* s_hw   = s_dst + 64;
    float* s_hw2  = s_hw  + 64;
    float* s_d2   = s_hw2 + 64;
    float* s_arow = s_d2  + 64;
    float* s_c    = s_arow + 64;
    float* s_v    = s_c   + 64;
    float* s_scal = s_v   + 128;
    unsigned long long* s_msk = (unsigned long long*)(s_scal + 4);

    const int tid  = threadIdx.x;
    const int w    = tid >> 5;
    const int lane = tid & 31;
    const int bt   = blockIdx.x;

    const float* xp = x + (size_t)bt * Nv * Fv;
    for (int i = tid; i < Nv * Fv; i += 256) s_x[i] = xp[i];
    if (tid < Nv) s_msk[tid] = gmsk[tid];
    __syncthreads();

    for (int idx = tid; idx < Nv * Hv; idx += 256) {
        int n = idx >> 7, o = idx & 127;
        float acc = 0.f;
#pragma unroll
        for (int f = 0; f < Fv; ++f)
            acc += s_x[n * Fv + f] * __ldg(&W1[f * Hv + o]);
        s_h[n * SH + o] = acc;
    }
    __syncthreads();

    {
        int grp = tid >> 6;
        int n = tid & 63;
        const float* vec = (grp == 0) ? a1
                         : (grp == 1) ? (a1 + Hv)
                         : (grp == 2) ? w2a : w2b;
        const float4* row = (const float4*)(s_h + n * SH);
        const float4* v4  = (const float4*)vec;
        float acc = 0.f;
#pragma unroll 8
        for (int i = 0; i < 32; ++i) {
            float4 hv = row[i];
            float4 av = __ldg(&v4[i]);
            acc += hv.x * av.x + hv.y * av.y + hv.z * av.z + hv.w * av.w;
        }
        float* dsts[4] = { s_src, s_dst, s_hw, s_hw2 };
        dsts[grp][n] = acc;
    }
    __syncthreads();

    for (int i = w; i < Nv; i += 8) {
        unsigned long long m = s_msk[i];
        float si = s_src[i];
        int j0 = lane, j1 = lane + 32;
        float v0 = si + s_dst[j0]; v0 = v0 > 0.f ? v0 : 0.2f * v0;
        float v1 = si + s_dst[j1]; v1 = v1 > 0.f ? v1 : 0.2f * v1;
        float e0 = ((m >> j0) & 1ull) ? v0 : -1e9f;
        float e1 = ((m >> j1) & 1ull) ? v1 : -1e9f;
        float mx = fmaxf(e0, e1);
#pragma unroll
        for (int off = 16; off; off >>= 1)
            mx = fmaxf(mx, __shfl_xor_sync(0xffffffffu, mx, off));
        float p0 = __expf(e0 - mx), p1 = __expf(e1 - mx);
        float s = p0 + p1;
#pragma unroll
        for (int off = 16; off; off >>= 1)
            s += __shfl_xor_sync(0xffffffffu, s, off);
        float inv = 1.f / s;
        s_attn[i * 65 + j0] = p0 * inv;
        s_attn[i * 65 + j1] = p1 * inv;
    }
    __syncthreads();

    int site = __ldg(site_ptr);
    if (tid < 64) {
        float acc = 0.f;
#pragma unroll 8
        for (int j = 0; j < Nv; ++j)
            acc += s_attn[tid * 65 + j] * s_hw[j];
        s_d2[tid] = acc;
    } else if (tid == 64) {
        float acc = 0.f;
#pragma unroll 8
        for (int j = 0; j < Nv; ++j)
            acc += s_attn[site * 65 + j] * s_hw2[j];
        s_scal[0] = acc;
    }
    __syncthreads();

    if (w == 0) {
        unsigned long long m = s_msk[site];
        float ss = s_scal[0];
        int j0 = lane, j1 = lane + 32;
        float v0 = ss + s_d2[j0]; v0 = v0 > 0.f ? v0 : 0.2f * v0;
        float v1 = ss + s_d2[j1]; v1 = v1 > 0.f ? v1 : 0.2f * v1;
        float e0 = ((m >> j0) & 1ull) ? v0 : -1e9f;
        float e1 = ((m >> j1) & 1ull) ? v1 : -1e9f;
        float mx = fmaxf(e0, e1);
#pragma unroll
        for (int off = 16; off; off >>= 1)
            mx = fmaxf(mx, __shfl_xor_sync(0xffffffffu, mx, off));
        float p0 = __expf(e0 - mx), p1 = __expf(e1 - mx);
        float s = p0 + p1;
#pragma unroll
        for (int off = 16; off; off >>= 1)
            s += __shfl_xor_sync(0xffffffffu, s, off);
        float inv = 1.f / s;
        s_arow[j0] = p0 * inv;
        s_arow[j1] = p1 * inv;
    }
    __syncthreads();

    if (tid < 64) {
        float acc = 0.f;
#pragma unroll 8
        for (int i = 0; i < Nv; ++i)
            acc += s_arow[i] * s_attn[i * 65 + tid];
        s_c[tid] = acc;
    }
    __syncthreads();

    if (tid < Hv) {
        float acc = 0.f;
#pragma unroll 8
        for (int j = 0; j < Nv; ++j)
            acc += s_c[j] * s_h[j * SH + tid];
        s_v[tid] = acc;
    }
    __syncthreads();

    {
        int o = tid & 127, hf = tid >> 7;
        float acc = 0.f;
        int k0 = hf * 64;
#pragma unroll 8
        for (int k = 0; k < 64; ++k)
            acc += s_v[k0 + k] * __ldg(&W2[(size_t)(k0 + k) * Hv + o]);
        if (hf == 1) s_hw[o] = acc;
        __syncthreads();
        if (hf == 0)
            seq_out[(size_t)bt * Hv + o] = acc + s_hw[o];
    }
}

// ---------------------------------------------------------------------------
__device__ __forceinline__ float sigm_fast(float x) {
    return 1.f / (1.f + __expf(-x));
}
__device__ __forceinline__ float tanh_fast(float x) {
    float t = __expf(2.f * fminf(fmaxf(x, -15.f), 15.f));
    return __fdividef(t - 1.f, t + 1.f);
}

// ---------------------------------------------------------------------------
// Pipelined LSTM: 128 persistent blocks = 4 layers x 32 batch-pairs.
// Layer l>0 consumes layer l-1's h(t) via global flags (release/acquire).
// Gate dot is the fused 256-wide [x_t ; h_{t-1}] @ WC row + bsum.
__global__ __launch_bounds__(512)
void lstm_pipe(const float* __restrict__ x0,       // layer-0 x = GAT output
               const float* __restrict__ WC,
               const float* __restrict__ bsum,
               float* __restrict__ hseq,           // [NL][BT*Hv]
               float* __restrict__ hfin,           // [NL][Bv*Hv]
               int* __restrict__ flags) {          // [NL][32]
    const int blk  = blockIdx.x;
    const int l    = blk >> 5;          // layer
    const int pair = blk & 31;
    const int b0   = pair * 2;
    const int u    = threadIdx.x;

    __shared__ __align__(16) float vsm[2][KW];   // [batch][x:128 | h:128]
    __shared__ float gsm[2][G4];

    const float* xin  = (l == 0) ? x0 : (hseq + (size_t)(l - 1) * BT * Hv);
    float*       hout = hseq + (size_t)l * BT * Hv;
    const ulonglong2* W2p = (const ulonglong2*)(WC + (size_t)l * WC_PER_L);
    const float bias = __ldg(&bsum[l * G4 + u]);
    int* fprod = flags + l * 32 + pair;
    int* fcons = flags + (l - 1) * 32 + pair;

    if (u < 256) vsm[u >> 7][Hv + (u & 127)] = 0.f;   // h(-1) = 0
    __syncthreads();

    const int bb = u >> 7, un = u & 127;    // for 256-thread phases
    float c = 0.f;

    for (int t = 0; t < Tv; ++t) {
        if (l > 0) {
            if (u == 0) {
                int v;
                do {
                    asm volatile("ld.acquire.gpu.b32 %0, [%1];"
                                 : "=r"(v) : "l"(fcons));
                } while (v < t + 1);
            }
            __syncthreads();
        }
        if (u < 256)
            vsm[bb][un] = xin[((size_t)(b0 + bb) * Tv + t) * Hv + un];
        __syncthreads();

        // gate GEMV: 256-wide dot per (batch, gate)
        const ulonglong2* v0 = (const ulonglong2*)vsm[0];
        const ulonglong2* v1 = (const ulonglong2*)vsm[1];
        unsigned long long a00 = 0ull, a01 = 0ull, a10 = 0ull, a11 = 0ull;
#pragma unroll 8
        for (int kb = 0; kb < 64; ++kb) {
            ulonglong2 wv = __ldg(&W2p[kb * G4 + u]);
            ulonglong2 x0v = v0[kb];
            ulonglong2 x1v = v1[kb];
            fma2(a00, wv.x, x0v.x); fma2(a01, wv.y, x0v.y);
            fma2(a10, wv.x, x1v.x); fma2(a11, wv.y, x1v.y);
        }
        F2U r0{.u = a00}, r1{.u = a01}, r2{.u = a10}, r3{.u = a11};
        gsm[0][u] = bias + r0.f.x + r0.f.y + r1.f.x + r1.f.y;
        gsm[1][u] = bias + r2.f.x + r2.f.y + r3.f.x + r3.f.y;
        __syncthreads();

        if (u < 256) {
            float gi = gsm[bb][un];
            float gf = gsm[bb][Hv + un];
            float gg = gsm[bb][2 * Hv + un];
            float go = gsm[bb][3 * Hv + un];
            c = sigm_fast(gf) * c + sigm_fast(gi) * tanh_fast(gg);
            float h = sigm_fast(go) * tanh_fast(c);
            vsm[bb][Hv + un] = h;
            hout[((size_t)(b0 + bb) * Tv + t) * Hv + un] = h;
            if (t == Tv - 1)
                hfin[(size_t)l * Bv * Hv + (b0 + bb) * Hv + un] = h;
        }
        __syncthreads();

        if (l < NL - 1 && u == 0) {
            int tv = t + 1;
            asm volatile("st.release.gpu.b32 [%0], %1;"
                         :: "l"(fprod), "r"(tv) : "memory");
        }
    }
}

// ---------------------------------------------------------------------------
__global__ void final_kernel(const float* __restrict__ hf,
                             const float* __restrict__ Wlin,
                             const float* __restrict__ blin,
                             float* __restrict__ out) {
    int b = threadIdx.x;
    if (b >= Bv) return;
    float acc = blin[0];
    for (int l = 0; l < NL; ++l)
        for (int k = 0; k < Hv; ++k)
            acc += hf[(size_t)l * Bv * Hv + b * Hv + k] * Wlin[l * Hv + k];
    out[b] = acc;
}

// ---------------------------------------------------------------------------
extern "C" void kernel_launch(void* const* d_in, const int* in_sizes, int n_in,
                              void* d_out, int out_size) {
    const float* x    = (const float*)d_in[0];
    const int*   adj  = (const int*)d_in[1];
    const float* W1   = (const float*)d_in[2];
    const float* a1   = (const float*)d_in[3];
    const float* W2   = (const float*)d_in[4];
    const float* a2   = (const float*)d_in[5];
    const float* Wih  = (const float*)d_in[6];
    const float* Whh  = (const float*)d_in[7];
    const float* bih  = (const float*)d_in[8];
    const float* bhh  = (const float*)d_in[9];
    const float* Wlin = (const float*)d_in[10];
    const float* blin = (const float*)d_in[11];
    const int*   site = (const int*)d_in[12];
    float* out = (float*)d_out;

    float *pA, *pHS, *pHF, *pWC, *pBS, *pW2a, *pW2b;
    unsigned long long* pM;
    int* pFL;
    cudaGetSymbolAddress((void**)&pA,   g_seqA);
    cudaGetSymbolAddress((void**)&pHS,  g_hseq);
    cudaGetSymbolAddress((void**)&pHF,  g_hfinal);
    cudaGetSymbolAddress((void**)&pWC,  g_WC);
    cudaGetSymbolAddress((void**)&pBS,  g_bsum);
    cudaGetSymbolAddress((void**)&pW2a, g_w2a);
    cudaGetSymbolAddress((void**)&pW2b, g_w2b);
    cudaGetSymbolAddress((void**)&pM,   g_msk);
    cudaGetSymbolAddress((void**)&pFL,  g_flags);

    cudaFuncSetAttribute(gat_kernel,
                         cudaFuncAttributeMaxDynamicSharedMemorySize, GAT_SMEM);

    mask_kernel<<<1, 64>>>(adj, pM);
    w2vec_kernel<<<1, 256>>>(W2, a2, pW2a, pW2b);
    build_wc_kernel<<<(NL * WC_PER_L + 255) / 256, 256>>>(Wih, Whh, pWC);
    bsum_kernel<<<(NL * G4 + 255) / 256, 256>>>(bih, bhh, pBS);
    flaginit_kernel<<<1, 128>>>(pFL);
    gat_kernel<<<BT, 256, GAT_SMEM>>>(x, W1, a1, W2, pW2a, pW2b, site, pM, pA);
    lstm_pipe<<<NL * 32, 512>>>(pA, pWC, pBS, pHS, pHF, pFL);
    final_kernel<<<1, 64>>>(pHF, Wlin, blin, out);
}

// round 15
// speedup vs baseline: 1.7523x; 1.0192x over previous
#include <cuda_runtime.h>
#include <cstddef>

// Problem constants
constexpr int Bv = 64, Tv = 168, Nv = 64, Fv = 17, Hv = 128;
constexpr int BT = Bv * Tv;            // 10752
constexpr int G4 = 4 * Hv;             // 512 gate units
constexpr int NL = 4;
constexpr int KW = 256;                // fused gate dot width (x:128 | h:128)
constexpr int WC_PER_L = G4 * KW;      // 131072 floats per layer

// Scratch (device globals — no allocation allowed)
__device__ float g_seqA[BT * Hv];                 // GAT output (layer-0 x)
__device__ float g_hseq[NL * BT * Hv];            // per-layer h sequences
__device__ float g_hfinal[NL * Bv * Hv];
__device__ float g_WC[NL * WC_PER_L];             // fused [l][kb][u][4]
__device__ float g_bsum[NL * G4];
__device__ float g_w2a[Hv];
__device__ float g_w2b[Hv];
__device__ unsigned long long g_msk[Nv];
__device__ int   g_flags[NL * 32];                // progress per (layer, pair)

// ---------------------------------------------------------------------------
// packed f32x2 FMA (Blackwell; only reachable via PTX)
union F2U { float2 f; unsigned long long u; };
__device__ __forceinline__ void fma2(unsigned long long& acc,
                                     unsigned long long a,
                                     unsigned long long b) {
    asm("fma.rn.f32x2 %0, %1, %2, %3;" : "=l"(acc) : "l"(a), "l"(b), "l"(acc));
}

// ---------------------------------------------------------------------------
__global__ void mask_kernel(const int* __restrict__ adj,
                            unsigned long long* __restrict__ msk) {
    int i = threadIdx.x;
    if (i >= Nv) return;
    unsigned long long m = 0ull;
    for (int j = 0; j < Nv; ++j)
        if (adj[i * Nv + j] > 0 || j == i) m |= (1ull << j);
    msk[i] = m;
}

// ---------------------------------------------------------------------------
__global__ void w2vec_kernel(const float* __restrict__ W2,
                             const float* __restrict__ a2,
                             float* __restrict__ w2a,
                             float* __restrict__ w2b) {
    int tid = threadIdx.x;        // 256 threads
    int k = tid & 127;
    const float* av = (tid < 128) ? (a2 + Hv) : a2;
    float acc = 0.f;
    for (int o = 0; o < Hv; ++o)
        acc += W2[(size_t)k * Hv + o] * av[o];
    if (tid < 128) w2a[k] = acc; else w2b[k] = acc;
}

// ---------------------------------------------------------------------------
// Build fused transposed weights: WC[l][kb][u][i] with k = kb*4+i,
// k<128 -> Wih[l][u][k], k>=128 -> Whh[l][u][k-128]. Also bsum.
__global__ void build_wc_kernel(const float* __restrict__ Wih,
                                const float* __restrict__ Whh,
                                float* __restrict__ WC) {
    int idx = blockIdx.x * 256 + threadIdx.x;
    if (idx >= NL * WC_PER_L) return;
    int l  = idx >> 17;            // / 131072
    int r  = idx & 131071;
    int kb = r >> 11;              // / 2048
    int r2 = r & 2047;
    int u  = r2 >> 2;
    int i  = r2 & 3;
    int k  = kb * 4 + i;
    float v;
    if (k < Hv) v = Wih[((size_t)l * G4 + u) * Hv + k];
    else        v = Whh[((size_t)l * G4 + u) * Hv + (k - Hv)];
    WC[idx] = v;
}

__global__ void bsum_kernel(const float* __restrict__ bih,
                            const float* __restrict__ bhh,
                            float* __restrict__ bsum) {
    int idx = blockIdx.x * 256 + threadIdx.x;
    if (idx < NL * G4) bsum[idx] = bih[idx] + bhh[idx];
}

__global__ void flaginit_kernel(int* __restrict__ flags) {
    if (threadIdx.x < NL * 32) flags[threadIdx.x] = 0;
}

// ---------------------------------------------------------------------------
// Fused GAT1 + GAT2 per (b,t) — unchanged from R11 (417us, not the bottleneck)
constexpr int SH = 132;
constexpr int GAT_FLOATS = 64 * SH + 64 * 65 + Nv * Fv + 7 * 64 + 128 + 4;
constexpr int GAT_SMEM = GAT_FLOATS * 4 + Nv * 8;

__global__ __launch_bounds__(256)
void gat_kernel(const float* __restrict__ x,
                const float* __restrict__ W1, const float* __restrict__ a1,
                const float* __restrict__ W2,
                const float* __restrict__ w2a, const float* __restrict__ w2b,
                const int* __restrict__ site_ptr,
                const unsigned long long* __restrict__ gmsk,
                float* __restrict__ seq_out) {
    extern __shared__ float sm[];
    float* s_h    = sm;
    float* s_attn = s_h   + 64 * SH;
    float* s_x    = s_attn + 64 * 65;
    float* s_src  = s_x   + Nv * Fv;
    float* s_dst  = s_src + 64;
    float* s_hw   = s_dst + 64;
    float* s_hw2  = s_hw  + 64;
    float* s_d2   = s_hw2 + 64;
    float* s_arow = s_d2  + 64;
    float* s_c    = s_arow + 64;
    float* s_v    = s_c   + 64;
    float* s_scal = s_v   + 128;
    unsigned long long* s_msk = (unsigned long long*)(s_scal + 4);

    const int tid  = threadIdx.x;
    const int w    = tid >> 5;
    const int lane = tid & 31;
    const int bt   = blockIdx.x;

    const float* xp = x + (size_t)bt * Nv * Fv;
    for (int i = tid; i < Nv * Fv; i += 256) s_x[i] = xp[i];
    if (tid < Nv) s_msk[tid] = gmsk[tid];
    __syncthreads();

    for (int idx = tid; idx < Nv * Hv; idx += 256) {
        int n = idx >> 7, o = idx & 127;
        float acc = 0.f;
#pragma unroll
        for (int f = 0; f < Fv; ++f)
            acc += s_x[n * Fv + f] * __ldg(&W1[f * Hv + o]);
        s_h[n * SH + o] = acc;
    }
    __syncthreads();

    {
        int grp = tid >> 6;
        int n = tid & 63;
        const float* vec = (grp == 0) ? a1
                         : (grp == 1) ? (a1 + Hv)
                         : (grp == 2) ? w2a : w2b;
        const float4* row = (const float4*)(s_h + n * SH);
        const float4* v4  = (const float4*)vec;
        float acc = 0.f;
#pragma unroll 8
        for (int i = 0; i < 32; ++i) {
            float4 hv = row[i];
            float4 av = __ldg(&v4[i]);
            acc += hv.x * av.x + hv.y * av.y + hv.z * av.z + hv.w * av.w;
        }
        float* dsts[4] = { s_src, s_dst, s_hw, s_hw2 };
        dsts[grp][n] = acc;
    }
    __syncthreads();

    for (int i = w; i < Nv; i += 8) {
        unsigned long long m = s_msk[i];
        float si = s_src[i];
        int j0 = lane, j1 = lane + 32;
        float v0 = si + s_dst[j0]; v0 = v0 > 0.f ? v0 : 0.2f * v0;
        float v1 = si + s_dst[j1]; v1 = v1 > 0.f ? v1 : 0.2f * v1;
        float e0 = ((m >> j0) & 1ull) ? v0 : -1e9f;
        float e1 = ((m >> j1) & 1ull) ? v1 : -1e9f;
        float mx = fmaxf(e0, e1);
#pragma unroll
        for (int off = 16; off; off >>= 1)
            mx = fmaxf(mx, __shfl_xor_sync(0xffffffffu, mx, off));
        float p0 = __expf(e0 - mx), p1 = __expf(e1 - mx);
        float s = p0 + p1;
#pragma unroll
        for (int off = 16; off; off >>= 1)
            s += __shfl_xor_sync(0xffffffffu, s, off);
        float inv = 1.f / s;
        s_attn[i * 65 + j0] = p0 * inv;
        s_attn[i * 65 + j1] = p1 * inv;
    }
    __syncthreads();

    int site = __ldg(site_ptr);
    if (tid < 64) {
        float acc = 0.f;
#pragma unroll 8
        for (int j = 0; j < Nv; ++j)
            acc += s_attn[tid * 65 + j] * s_hw[j];
        s_d2[tid] = acc;
    } else if (tid == 64) {
        float acc = 0.f;
#pragma unroll 8
        for (int j = 0; j < Nv; ++j)
            acc += s_attn[site * 65 + j] * s_hw2[j];
        s_scal[0] = acc;
    }
    __syncthreads();

    if (w == 0) {
        unsigned long long m = s_msk[site];
        float ss = s_scal[0];
        int j0 = lane, j1 = lane + 32;
        float v0 = ss + s_d2[j0]; v0 = v0 > 0.f ? v0 : 0.2f * v0;
        float v1 = ss + s_d2[j1]; v1 = v1 > 0.f ? v1 : 0.2f * v1;
        float e0 = ((m >> j0) & 1ull) ? v0 : -1e9f;
        float e1 = ((m >> j1) & 1ull) ? v1 : -1e9f;
        float mx = fmaxf(e0, e1);
#pragma unroll
        for (int off = 16; off; off >>= 1)
            mx = fmaxf(mx, __shfl_xor_sync(0xffffffffu, mx, off));
        float p0 = __expf(e0 - mx), p1 = __expf(e1 - mx);
        float s = p0 + p1;
#pragma unroll
        for (int off = 16; off; off >>= 1)
            s += __shfl_xor_sync(0xffffffffu, s, off);
        float inv = 1.f / s;
        s_arow[j0] = p0 * inv;
        s_arow[j1] = p1 * inv;
    }
    __syncthreads();

    if (tid < 64) {
        float acc = 0.f;
#pragma unroll 8
        for (int i = 0; i < Nv; ++i)
            acc += s_arow[i] * s_attn[i * 65 + tid];
        s_c[tid] = acc;
    }
    __syncthreads();

    if (tid < Hv) {
        float acc = 0.f;
#pragma unroll 8
        for (int j = 0; j < Nv; ++j)
            acc += s_c[j] * s_h[j * SH + tid];
        s_v[tid] = acc;
    }
    __syncthreads();

    {
        int o = tid & 127, hf = tid >> 7;
        float acc = 0.f;
        int k0 = hf * 64;
#pragma unroll 8
        for (int k = 0; k < 64; ++k)
            acc += s_v[k0 + k] * __ldg(&W2[(size_t)(k0 + k) * Hv + o]);
        if (hf == 1) s_hw[o] = acc;
        __syncthreads();
        if (hf == 0)
            seq_out[(size_t)bt * Hv + o] = acc + s_hw[o];
    }
}

// ---------------------------------------------------------------------------
__device__ __forceinline__ float sigm_fast(float x) {
    return 1.f / (1.f + __expf(-x));
}
__device__ __forceinline__ float tanh_fast(float x) {
    float t = __expf(2.f * fminf(fmaxf(x, -15.f), 15.f));
    return __fdividef(t - 1.f, t + 1.f);
}

// ---------------------------------------------------------------------------
// Pipelined LSTM: 128 persistent blocks = 4 layers x 32 batch-pairs.
// Layer l>0 consumes layer l-1's h(t) via global flags (release/acquire).
// Gate dot is the fused 256-wide [x_t ; h_{t-1}] @ WC row + bsum.
__global__ __launch_bounds__(512)
void lstm_pipe(const float* __restrict__ x0,       // layer-0 x = GAT output
               const float* __restrict__ WC,
               const float* __restrict__ bsum,
               float* __restrict__ hseq,           // [NL][BT*Hv]
               float* __restrict__ hfin,           // [NL][Bv*Hv]
               int* __restrict__ flags) {          // [NL][32]
    const int blk  = blockIdx.x;
    const int l    = blk >> 5;          // layer
    const int pair = blk & 31;
    const int b0   = pair * 2;
    const int u    = threadIdx.x;

    __shared__ __align__(16) float vsm[2][KW];   // [batch][x:128 | h:128]
    __shared__ float gsm[2][G4];

    const float* xin  = (l == 0) ? x0 : (hseq + (size_t)(l - 1) * BT * Hv);
    float*       hout = hseq + (size_t)l * BT * Hv;
    const ulonglong2* W2p = (const ulonglong2*)(WC + (size_t)l * WC_PER_L);
    const float bias = __ldg(&bsum[l * G4 + u]);
    int* fprod = flags + l * 32 + pair;
    int* fcons = flags + (l - 1) * 32 + pair;

    if (u < 256) vsm[u >> 7][Hv + (u & 127)] = 0.f;   // h(-1) = 0
    __syncthreads();

    const int bb = u >> 7, un = u & 127;    // for 256-thread phases
    float c = 0.f;

    for (int t = 0; t < Tv; ++t) {
        if (l > 0) {
            if (u == 0) {
                int v;
                do {
                    asm volatile("ld.acquire.gpu.b32 %0, [%1];"
                                 : "=r"(v) : "l"(fcons));
                } while (v < t + 1);
            }
            __syncthreads();
        }
        if (u < 256)
            vsm[bb][un] = xin[((size_t)(b0 + bb) * Tv + t) * Hv + un];
        __syncthreads();

        // gate GEMV: 256-wide dot per (batch, gate)
        const ulonglong2* v0 = (const ulonglong2*)vsm[0];
        const ulonglong2* v1 = (const ulonglong2*)vsm[1];
        unsigned long long a00 = 0ull, a01 = 0ull, a10 = 0ull, a11 = 0ull;
#pragma unroll 8
        for (int kb = 0; kb < 64; ++kb) {
            ulonglong2 wv = __ldg(&W2p[kb * G4 + u]);
            ulonglong2 x0v = v0[kb];
            ulonglong2 x1v = v1[kb];
            fma2(a00, wv.x, x0v.x); fma2(a01, wv.y, x0v.y);
            fma2(a10, wv.x, x1v.x); fma2(a11, wv.y, x1v.y);
        }
        F2U r0{.u = a00}, r1{.u = a01}, r2{.u = a10}, r3{.u = a11};
        gsm[0][u] = bias + r0.f.x + r0.f.y + r1.f.x + r1.f.y;
        gsm[1][u] = bias + r2.f.x + r2.f.y + r3.f.x + r3.f.y;
        __syncthreads();

        if (u < 256) {
            float gi = gsm[bb][un];
            float gf = gsm[bb][Hv + un];
            float gg = gsm[bb][2 * Hv + un];
            float go = gsm[bb][3 * Hv + un];
            c = sigm_fast(gf) * c + sigm_fast(gi) * tanh_fast(gg);
            float h = sigm_fast(go) * tanh_fast(c);
            vsm[bb][Hv + un] = h;
            hout[((size_t)(b0 + bb) * Tv + t) * Hv + un] = h;
            if (t == Tv - 1)
                hfin[(size_t)l * Bv * Hv + (b0 + bb) * Hv + un] = h;
        }
        __syncthreads();

        if (l < NL - 1 && u == 0) {
            int tv = t + 1;
            asm volatile("st.release.gpu.b32 [%0], %1;"
                         :: "l"(fprod), "r"(tv) : "memory");
        }
    }
}

// ---------------------------------------------------------------------------
__global__ void final_kernel(const float* __restrict__ hf,
                             const float* __restrict__ Wlin,
                             const float* __restrict__ blin,
                             float* __restrict__ out) {
    int b = threadIdx.x;
    if (b >= Bv) return;
    float acc = blin[0];
    for (int l = 0; l < NL; ++l)
        for (int k = 0; k < Hv; ++k)
            acc += hf[(size_t)l * Bv * Hv + b * Hv + k] * Wlin[l * Hv + k];
    out[b] = acc;
}

// ---------------------------------------------------------------------------
extern "C" void kernel_launch(void* const* d_in, const int* in_sizes, int n_in,
                              void* d_out, int out_size) {
    const float* x    = (const float*)d_in[0];
    const int*   adj  = (const int*)d_in[1];
    const float* W1   = (const float*)d_in[2];
    const float* a1   = (const float*)d_in[3];
    const float* W2   = (const float*)d_in[4];
    const float* a2   = (const float*)d_in[5];
    const float* Wih  = (const float*)d_in[6];
    const float* Whh  = (const float*)d_in[7];
    const float* bih  = (const float*)d_in[8];
    const float* bhh  = (const float*)d_in[9];
    const float* Wlin = (const float*)d_in[10];
    const float* blin = (const float*)d_in[11];
    const int*   site = (const int*)d_in[12];
    float* out = (float*)d_out;

    float *pA, *pHS, *pHF, *pWC, *pBS, *pW2a, *pW2b;
    unsigned long long* pM;
    int* pFL;
    cudaGetSymbolAddress((void**)&pA,   g_seqA);
    cudaGetSymbolAddress((void**)&pHS,  g_hseq);
    cudaGetSymbolAddress((void**)&pHF,  g_hfinal);
    cudaGetSymbolAddress((void**)&pWC,  g_WC);
    cudaGetSymbolAddress((void**)&pBS,  g_bsum);
    cudaGetSymbolAddress((void**)&pW2a, g_w2a);
    cudaGetSymbolAddress((void**)&pW2b, g_w2b);
    cudaGetSymbolAddress((void**)&pM,   g_msk);
    cudaGetSymbolAddress((void**)&pFL,  g_flags);

    cudaFuncSetAttribute(gat_kernel,
                         cudaFuncAttributeMaxDynamicSharedMemorySize, GAT_SMEM);

    mask_kernel<<<1, 64>>>(adj, pM);
    w2vec_kernel<<<1, 256>>>(W2, a2, pW2a, pW2b);
    build_wc_kernel<<<(NL * WC_PER_L + 255) / 256, 256>>>(Wih, Whh, pWC);
    bsum_kernel<<<(NL * G4 + 255) / 256, 256>>>(bih, bhh, pBS);
    flaginit_kernel<<<1, 128>>>(pFL);
    gat_kernel<<<BT, 256, GAT_SMEM>>>(x, W1, a1, W2, pW2a, pW2b, site, pM, pA);
    lstm_pipe<<<NL * 32, 512>>>(pA, pWC, pBS, pHS, pHF, pFL);
    final_kernel<<<1, 64>>>(pHF, Wlin, blin, out);
}